// round 2
// baseline (speedup 1.0000x reference)
#include <cuda_runtime.h>

// LuongAttention: O[b] = (Q Eᵀ) E == Q (EᵀE).  G = EᵀE is 128x128 per batch.
// 8x fewer FLOPs than reference order.  Inner loops use packed fma.rn.f32x2
// (Blackwell FFMA2): 2 fp32 FMAs per issue slot — ptxas never auto-fuses this,
// so we emit it by hand.  B=8, T=2048, D=128.

#define BB      8
#define TT      2048
#define DD      128
#define NSPLIT  16
#define KCHUNK  (TT / NSPLIT)        // 128

typedef unsigned long long u64;

__device__ float g_part[BB * NSPLIT * DD * DD];  // 8 MB partial EᵀE
__device__ float g_full[BB * DD * DD];           // 512 KB reduced G

__device__ __forceinline__ u64 pack2(float x, float y) {
    u64 r;
    asm("mov.b64 %0, {%1, %2};" : "=l"(r) : "f"(x), "f"(y));
    return r;
}
__device__ __forceinline__ void fma2(u64& d, u64 a, u64 b) {
    asm("fma.rn.f32x2 %0, %1, %2, %0;" : "+l"(d) : "l"(a), "l"(b));
}
__device__ __forceinline__ float2 unpack2(u64 v) {
    float2 f;
    asm("mov.b64 {%0, %1}, %2;" : "=f"(f.x), "=f"(f.y) : "l"(v));
    return f;
}

// ---------------------------------------------------------------------------
// Kernel 1: partial G.  CTA (sp, b): g_part[b][sp] = E_chunkᵀ E_chunk (128³).
// 256 threads, 8x8 register tile each; j-dimension packed in f32x2 pairs.
// ---------------------------------------------------------------------------
__global__ __launch_bounds__(256) void ete_partial(const float* __restrict__ enc) {
    extern __shared__ float s[];                 // [128][128] chunk, row = k
    const int tid = threadIdx.x;
    const int b = blockIdx.y, sp = blockIdx.x;

    const float4* src =
        (const float4*)(enc + (size_t)(b * NSPLIT + sp) * (KCHUNK * DD));
    float4* s4 = (float4*)s;
#pragma unroll
    for (int v = 0; v < 16; v++)
        s4[tid + v * 256] = src[tid + v * 256];
    __syncthreads();

    const int tx = tid & 15, ty = tid >> 4;
    const int i0 = ty * 8, j0 = tx * 8;

    u64 acc[8][4];
#pragma unroll
    for (int ii = 0; ii < 8; ii++)
#pragma unroll
        for (int jj = 0; jj < 4; jj++) acc[ii][jj] = 0ULL;

#pragma unroll 4
    for (int k = 0; k < 128; k++) {
        const float* row = s + k * 128;
        float a[8];
        *(float4*)&a[0] = *(const float4*)&row[i0];
        *(float4*)&a[4] = *(const float4*)&row[i0 + 4];
        const ulonglong2* bp = (const ulonglong2*)&row[j0];   // 32B-aligned
        ulonglong2 b01 = bp[0], b23 = bp[1];
        u64 bv[4] = {b01.x, b01.y, b23.x, b23.y};
        u64 a2[8];
#pragma unroll
        for (int ii = 0; ii < 8; ii++) a2[ii] = pack2(a[ii], a[ii]);
#pragma unroll
        for (int ii = 0; ii < 8; ii++)
#pragma unroll
            for (int jj = 0; jj < 4; jj++)
                fma2(acc[ii][jj], a2[ii], bv[jj]);
    }

    float* outp = g_part + ((size_t)(b * NSPLIT + sp) << 14);
#pragma unroll
    for (int ii = 0; ii < 8; ii++) {
        float2 c0 = unpack2(acc[ii][0]), c1 = unpack2(acc[ii][1]);
        float2 c2 = unpack2(acc[ii][2]), c3 = unpack2(acc[ii][3]);
        float* r = outp + (i0 + ii) * 128 + j0;
        *(float4*)&r[0] = make_float4(c0.x, c0.y, c1.x, c1.y);
        *(float4*)&r[4] = make_float4(c2.x, c2.y, c3.x, c3.y);
    }
}

// ---------------------------------------------------------------------------
// Kernel 2: reduce partials (fixed order, deterministic), float4-vectorized.
// ---------------------------------------------------------------------------
__global__ __launch_bounds__(256) void reduce_g() {
    const int e4 = blockIdx.x * 256 + threadIdx.x;  // 0 .. 32767 float4s
    const int b = e4 >> 12;                          // 4096 float4 per batch
    const int r = e4 & 4095;
    const float4* base = (const float4*)g_part;
    float4 sum = make_float4(0.f, 0.f, 0.f, 0.f);
#pragma unroll
    for (int sp = 0; sp < NSPLIT; sp++) {
        float4 v = base[(size_t)(b * NSPLIT + sp) * 4096 + r];
        sum.x += v.x; sum.y += v.y; sum.z += v.z; sum.w += v.w;
    }
    ((float4*)g_full)[e4] = sum;
}

// ---------------------------------------------------------------------------
// Kernel 3: O_tile = Q_tile(128x128) @ G[b](128x128).  Same FFMA2 scheme.
// Qt transposed, stride 129; Gs row-major stride 128 (j-pairs 8B aligned).
// ---------------------------------------------------------------------------
__global__ __launch_bounds__(256) void qg_kernel(const float* __restrict__ dec,
                                                 float* __restrict__ out) {
    extern __shared__ float s[];
    float* Qt = s;                    // [k][i], stride 129
    float* Gs = s + 128 * 129;        // [k][j], stride 128
    const int tid = threadIdx.x;
    const int b = blockIdx.y, qt = blockIdx.x;

    const float4* qsrc = (const float4*)(dec + ((size_t)(b * 16 + qt) << 14));
#pragma unroll
    for (int v = 0; v < 16; v++) {
        int idx = tid + v * 256;
        int i  = idx >> 5;
        int k4 = idx & 31;
        float4 q = qsrc[idx];
        Qt[(k4 * 4 + 0) * 129 + i] = q.x;
        Qt[(k4 * 4 + 1) * 129 + i] = q.y;
        Qt[(k4 * 4 + 2) * 129 + i] = q.z;
        Qt[(k4 * 4 + 3) * 129 + i] = q.w;
    }
    const float4* gsrc = (const float4*)(g_full + ((size_t)b << 14));
    float4* g4 = (float4*)Gs;
#pragma unroll
    for (int v = 0; v < 16; v++)
        g4[tid + v * 256] = gsrc[tid + v * 256];
    __syncthreads();

    const int tx = tid & 15, ty = tid >> 4;
    const int i0 = ty * 8, j0 = tx * 8;

    u64 acc[8][4];
#pragma unroll
    for (int ii = 0; ii < 8; ii++)
#pragma unroll
        for (int jj = 0; jj < 4; jj++) acc[ii][jj] = 0ULL;

#pragma unroll 4
    for (int k = 0; k < 128; k++) {
        const float* qrow = Qt + k * 129 + i0;
        float a[8];
#pragma unroll
        for (int ii = 0; ii < 8; ii++) a[ii] = qrow[ii];
        const ulonglong2* bp = (const ulonglong2*)(Gs + k * 128 + j0);
        ulonglong2 b01 = bp[0], b23 = bp[1];
        u64 bv[4] = {b01.x, b01.y, b23.x, b23.y};
        u64 a2[8];
#pragma unroll
        for (int ii = 0; ii < 8; ii++) a2[ii] = pack2(a[ii], a[ii]);
#pragma unroll
        for (int ii = 0; ii < 8; ii++)
#pragma unroll
            for (int jj = 0; jj < 4; jj++)
                fma2(acc[ii][jj], a2[ii], bv[jj]);
    }

    float* obase = out + ((size_t)(b * 16 + qt) << 14);
#pragma unroll
    for (int ii = 0; ii < 8; ii++) {
        float2 c0 = unpack2(acc[ii][0]), c1 = unpack2(acc[ii][1]);
        float2 c2 = unpack2(acc[ii][2]), c3 = unpack2(acc[ii][3]);
        float* r = obase + (i0 + ii) * 128 + j0;
        *(float4*)&r[0] = make_float4(c0.x, c0.y, c1.x, c1.y);
        *(float4*)&r[4] = make_float4(c2.x, c2.y, c3.x, c3.y);
    }
}

// ---------------------------------------------------------------------------
// Launch
// ---------------------------------------------------------------------------
extern "C" void kernel_launch(void* const* d_in, const int* in_sizes, int n_in,
                              void* d_out, int out_size) {
    const float* enc = (const float*)d_in[0];
    const float* dec = (const float*)d_in[1];
    float* out = (float*)d_out;

    const int smem1 = 128 * 128 * 4;                   // 64 KB
    const int smem3 = (128 * 129 + 128 * 128) * 4;     // ~128.5 KB
    cudaFuncSetAttribute(ete_partial, cudaFuncAttributeMaxDynamicSharedMemorySize, smem1);
    cudaFuncSetAttribute(qg_kernel,   cudaFuncAttributeMaxDynamicSharedMemorySize, smem3);

    ete_partial<<<dim3(NSPLIT, BB), 256, smem1>>>(enc);
    reduce_g<<<(BB * DD * DD / 4) / 256, 256>>>();
    qg_kernel<<<dim3(TT / 128, BB), 256, smem3>>>(dec, out);
}

// round 4
// speedup vs baseline: 1.7722x; 1.7722x over previous
#include <cuda_runtime.h>
#include <cuda_bf16.h>
#include <cstdint>

// LuongAttention: O[b] = (Q Eᵀ) E == Q (EᵀE).  G = EᵀE per batch (128x128).
// Tensor-core path via baseline-PTX mma.sync (HMMA) bf16 — tcgen05 is not
// available at the harness's compute_103 PTX target.
// Precision: fp32 x = hi + lo (two bf16); x·y ≈ hi·hi + hi·lo + lo·hi with
// fp32 accumulation (drops lo·lo ~2^-18 rel).  B=8, T=2048, D=128.

#define BB 8
#define TT 2048
#define DD 128
#define NSPLIT 16

#define RSTRIDE 272            // bf16 plane row stride in BYTES (17*16)
#define PLANE   (128 * RSTRIDE)

__device__ float g_part[BB * NSPLIT * DD * DD];  // 8 MB partial EᵀE
__device__ float g_full[BB * DD * DD];           // 512 KB reduced G

// ---------------- helpers ----------------
__device__ __forceinline__ uint32_t smem_u32(const void* p) {
    uint32_t a;
    asm("{ .reg .u64 t; cvta.to.shared.u64 t, %1; cvt.u32.u64 %0, t; }"
        : "=r"(a) : "l"(p));
    return a;
}
__device__ __forceinline__ void ldsm_x4(uint32_t (&r)[4], uint32_t addr) {
    asm volatile("ldmatrix.sync.aligned.m8n8.x4.shared.b16 {%0,%1,%2,%3}, [%4];"
                 : "=r"(r[0]), "=r"(r[1]), "=r"(r[2]), "=r"(r[3]) : "r"(addr));
}
__device__ __forceinline__ void mma16816(float (&d)[4], const uint32_t (&a)[4],
                                         uint32_t b0, uint32_t b1) {
    asm volatile(
        "mma.sync.aligned.m16n8k16.row.col.f32.bf16.bf16.f32 "
        "{%0,%1,%2,%3}, {%4,%5,%6,%7}, {%8,%9}, {%0,%1,%2,%3};"
        : "+f"(d[0]), "+f"(d[1]), "+f"(d[2]), "+f"(d[3])
        : "r"(a[0]), "r"(a[1]), "r"(a[2]), "r"(a[3]), "r"(b0), "r"(b1));
}
// Split two fp32 into packed bf16x2 hi/lo planes (f0 -> low half).
__device__ __forceinline__ void split2(float f0, float f1, uint32_t& hi, uint32_t& lo) {
    asm("cvt.rn.bf16x2.f32 %0, %1, %2;" : "=r"(hi) : "f"(f1), "f"(f0));
    float h0 = __uint_as_float(hi << 16);
    float h1 = __uint_as_float(hi & 0xffff0000u);
    asm("cvt.rn.bf16x2.f32 %0, %1, %2;" : "=r"(lo) : "f"(f1 - h1), "f"(f0 - h0));
}

// Warp-level 64x32 GEMM mainloop over K=128 for one (Ahi,Alo,Bhi,Blo) set.
// A plane: [row i][k] bf16 stride RSTRIDE.  B plane: [row n][k] same layout.
__device__ __forceinline__ void warp_gemm(uint32_t aHi, uint32_t aLo,
                                          uint32_t bHi, uint32_t bLo,
                                          int wm, int wn, int lid,
                                          float (&acc)[4][4][4]) {
    // Per-lane intra-tile offsets (bytes).
    const int a_row = (lid & 15);               // + ((lid>>4)?col+8:0)
    const int a_coff = (lid >> 4) << 3;         // k offset (elements)
    const int b_row = ((lid >> 4) << 3) + (lid & 7);
    const int b_coff = ((lid >> 3) & 1) << 3;

#pragma unroll
    for (int kk = 0; kk < 8; kk++) {
        const int k0 = kk * 16;
        uint32_t Ah[4][4], Al[4][4], Bh[2][4], Bl[2][4];
#pragma unroll
        for (int mi = 0; mi < 4; mi++) {
            uint32_t off = (uint32_t)(wm + mi * 16 + a_row) * RSTRIDE +
                           (uint32_t)(k0 + a_coff) * 2;
            ldsm_x4(Ah[mi], aHi + off);
            ldsm_x4(Al[mi], aLo + off);
        }
#pragma unroll
        for (int np = 0; np < 2; np++) {
            uint32_t off = (uint32_t)(wn + np * 16 + b_row) * RSTRIDE +
                           (uint32_t)(k0 + b_coff) * 2;
            ldsm_x4(Bh[np], bHi + off);
            ldsm_x4(Bl[np], bLo + off);
        }
#pragma unroll
        for (int mi = 0; mi < 4; mi++)
#pragma unroll
            for (int nj = 0; nj < 4; nj++) {
                const int np = nj >> 1, pr = (nj & 1) << 1;
                mma16816(acc[mi][nj], Ah[mi], Bh[np][pr], Bh[np][pr + 1]);
                mma16816(acc[mi][nj], Ah[mi], Bl[np][pr], Bl[np][pr + 1]);
                mma16816(acc[mi][nj], Al[mi], Bh[np][pr], Bh[np][pr + 1]);
            }
    }
}

__device__ __forceinline__ void warp_epilogue(float* outp, int wm, int wn, int lid,
                                              float (&acc)[4][4][4]) {
    const int g = lid >> 2, tig = lid & 3;
#pragma unroll
    for (int mi = 0; mi < 4; mi++)
#pragma unroll
        for (int nj = 0; nj < 4; nj++) {
            const int row = wm + mi * 16 + g;
            const int col = wn + nj * 8 + 2 * tig;
            *(float2*)(outp + row * 128 + col) =
                make_float2(acc[mi][nj][0], acc[mi][nj][1]);
            *(float2*)(outp + (row + 8) * 128 + col) =
                make_float2(acc[mi][nj][2], acc[mi][nj][3]);
        }
}

// SMEM offsets (bytes)
#define K1_STG 0                       // fp32 staging [128][129] = 66048
#define K1_HI  66048
#define K1_LO  (66048 + PLANE)
#define K1_SZ  (66048 + 2 * PLANE)     // 135680
#define K3_QHI 0
#define K3_QLO PLANE
#define K3_GHI (2 * PLANE)
#define K3_GLO (3 * PLANE)
#define K3_SZ  (4 * PLANE)             // 139264

// ---------------------------------------------------------------------------
// Kernel 1: g_part[b][sp] = E_chunkᵀ E_chunk  (chunk = [128 tok][128 d]).
// ---------------------------------------------------------------------------
__global__ __launch_bounds__(256) void ete_hmma(const float* __restrict__ enc) {
    extern __shared__ char smem[];
    const uint32_t sb = smem_u32(smem);
    float* stg = (float*)(smem + K1_STG);
    const int tid = threadIdx.x, wid = tid >> 5, lid = tid & 31;
    const int b = blockIdx.y, sp = blockIdx.x;

    // Stage fp32 chunk [t][d], stride 129.
    const float4* src = (const float4*)(enc + (size_t)(b * NSPLIT + sp) * 128 * 128);
#pragma unroll
    for (int v = 0; v < 16; v++) {
        int idx = tid + v * 256;
        int t = idx >> 5, d4 = idx & 31;
        float4 q = src[idx];
        float* p = stg + t * 129 + d4 * 4;
        p[0] = q.x; p[1] = q.y; p[2] = q.z; p[3] = q.w;
    }
    __syncthreads();

    // Transpose + split: plane[row=d][k=t], bf16 hi/lo.
#pragma unroll
    for (int v = 0; v < 32; v++) {
        int idx = tid + v * 256;          // 0..8191 (d, t-pair)
        int d = idx >> 6, t2 = idx & 63, t = t2 * 2;
        uint32_t hi, lo;
        split2(stg[t * 129 + d], stg[(t + 1) * 129 + d], hi, lo);
        uint32_t off = (uint32_t)d * RSTRIDE + (uint32_t)t * 2;
        *(uint32_t*)(smem + K1_HI + off) = hi;
        *(uint32_t*)(smem + K1_LO + off) = lo;
    }
    __syncthreads();

    const int wm = (wid >> 2) * 64, wn = (wid & 3) * 32;
    float acc[4][4][4];
#pragma unroll
    for (int mi = 0; mi < 4; mi++)
#pragma unroll
        for (int nj = 0; nj < 4; nj++)
#pragma unroll
            for (int r = 0; r < 4; r++) acc[mi][nj][r] = 0.0f;

    warp_gemm(sb + K1_HI, sb + K1_LO, sb + K1_HI, sb + K1_LO, wm, wn, lid, acc);
    warp_epilogue(g_part + ((size_t)(b * NSPLIT + sp) << 14), wm, wn, lid, acc);
}

// ---------------------------------------------------------------------------
// Kernel 2: reduce partials (fixed order, deterministic).
// ---------------------------------------------------------------------------
__global__ __launch_bounds__(256) void reduce_g() {
    const int e4 = blockIdx.x * 256 + threadIdx.x;  // 0..32767 float4s
    const int b = e4 >> 12;
    const int r = e4 & 4095;
    const float4* base = (const float4*)g_part;
    float4 sum = make_float4(0.f, 0.f, 0.f, 0.f);
#pragma unroll
    for (int sp = 0; sp < NSPLIT; sp++) {
        float4 v = base[(size_t)(b * NSPLIT + sp) * 4096 + r];
        sum.x += v.x; sum.y += v.y; sum.z += v.z; sum.w += v.w;
    }
    ((float4*)g_full)[e4] = sum;
}

// ---------------------------------------------------------------------------
// Kernel 3: O_tile = Q_tile(128x128) @ G[b].  G symmetric -> rows are the
// col-major B operand.  No transposes needed.
// ---------------------------------------------------------------------------
__global__ __launch_bounds__(256) void qg_hmma(const float* __restrict__ dec,
                                               float* __restrict__ out) {
    extern __shared__ char smem[];
    const uint32_t sb = smem_u32(smem);
    const int tid = threadIdx.x, wid = tid >> 5, lid = tid & 31;
    const int b = blockIdx.y, qt = blockIdx.x;

    // Q tile: [q][d] K-major, split into hi/lo planes.
    const float4* qsrc = (const float4*)(dec + ((size_t)(b * 16 + qt) << 14));
#pragma unroll
    for (int v = 0; v < 16; v++) {
        int idx = tid + v * 256;
        int row = idx >> 5, d4 = idx & 31;
        float4 q = qsrc[idx];
        uint32_t h0, l0, h1, l1;
        split2(q.x, q.y, h0, l0);
        split2(q.z, q.w, h1, l1);
        uint32_t off = (uint32_t)row * RSTRIDE + (uint32_t)d4 * 8;
        *(uint2*)(smem + K3_QHI + off) = make_uint2(h0, h1);
        *(uint2*)(smem + K3_QLO + off) = make_uint2(l0, l1);
    }
    // G tile: [j][d] (symmetric).
    const float4* gsrc = (const float4*)(g_full + ((size_t)b << 14));
#pragma unroll
    for (int v = 0; v < 16; v++) {
        int idx = tid + v * 256;
        int row = idx >> 5, d4 = idx & 31;
        float4 g = gsrc[idx];
        uint32_t h0, l0, h1, l1;
        split2(g.x, g.y, h0, l0);
        split2(g.z, g.w, h1, l1);
        uint32_t off = (uint32_t)row * RSTRIDE + (uint32_t)d4 * 8;
        *(uint2*)(smem + K3_GHI + off) = make_uint2(h0, h1);
        *(uint2*)(smem + K3_GLO + off) = make_uint2(l0, l1);
    }
    __syncthreads();

    const int wm = (wid >> 2) * 64, wn = (wid & 3) * 32;
    float acc[4][4][4];
#pragma unroll
    for (int mi = 0; mi < 4; mi++)
#pragma unroll
        for (int nj = 0; nj < 4; nj++)
#pragma unroll
            for (int r = 0; r < 4; r++) acc[mi][nj][r] = 0.0f;

    warp_gemm(sb + K3_QHI, sb + K3_QLO, sb + K3_GHI, sb + K3_GLO, wm, wn, lid, acc);
    warp_epilogue(out + ((size_t)(b * 16 + qt) << 14), wm, wn, lid, acc);
}

// ---------------------------------------------------------------------------
// Launch
// ---------------------------------------------------------------------------
extern "C" void kernel_launch(void* const* d_in, const int* in_sizes, int n_in,
                              void* d_out, int out_size) {
    const float* enc = (const float*)d_in[0];
    const float* dec = (const float*)d_in[1];
    float* out = (float*)d_out;

    cudaFuncSetAttribute(ete_hmma, cudaFuncAttributeMaxDynamicSharedMemorySize, K1_SZ);
    cudaFuncSetAttribute(qg_hmma,  cudaFuncAttributeMaxDynamicSharedMemorySize, K3_SZ);

    ete_hmma<<<dim3(NSPLIT, BB), 256, K1_SZ>>>(enc);
    reduce_g<<<(BB * DD * DD / 4) / 256, 256>>>();
    qg_hmma<<<dim3(TT / 128, BB), 256, K3_SZ>>>(dec, out);
}